// round 16
// baseline (speedup 1.0000x reference)
#include <cuda_runtime.h>
#include <cuda_fp16.h>
#include <stdint.h>
#include <math.h>

#define N_NODES 50000
#define N_EDGES 800000
#define DIM_IN  256
#define DIM_HID 128
#define DIM_OUT 64
#define SCAN_BLOCKS ((N_NODES + 1023) / 1024)   // 49

// ---------------- device scratch (no allocation allowed) ----------------
// g_cnt / g_scanstate: zero at load; self-cleaned every call (deterministic).
__device__ float  g_dinv[N_NODES];
__device__ __half g_xh[N_NODES * DIM_IN];
__device__ __half g_w1t[DIM_HID * DIM_IN];   // W1^T fp16 [N][K]
__device__ __half g_w2t[DIM_OUT * DIM_HID];  // W2^T fp16 [N][K]
__device__ __half g_h1[N_NODES * DIM_HID];
__device__ __half g_y1[N_NODES * DIM_HID];
__device__ __half g_h2[N_NODES * DIM_OUT];
__device__ int   g_src[N_EDGES];
__device__ int   g_dst[N_EDGES];
__device__ int   g_cnt[N_NODES];
__device__ int   g_row_ptr[N_NODES + 1];
__device__ int   g_fill[N_NODES];
__device__ int2  g_col[N_EDGES];             // packed {src, dinv[src] bits}
__device__ unsigned long long g_scanstate[SCAN_BLOCKS];

// ---------------- fused converter: blocks [0,192) weights, rest x ----------------
#define WT_BLOCKS (DIM_HID + DIM_OUT)        // 192
#define X_GROUPS  (N_NODES * DIM_IN / 8)
__global__ void convert_all_kernel(const float* __restrict__ x,
                                   __half* __restrict__ xh,
                                   const float* __restrict__ W1,
                                   __half* __restrict__ W1t,
                                   const float* __restrict__ W2,
                                   __half* __restrict__ W2t) {
    int b = blockIdx.x;
    if (b < DIM_HID) {
        for (int k = threadIdx.x; k < DIM_IN; k += blockDim.x)
            W1t[(size_t)b * DIM_IN + k] = __float2half_rn(W1[(size_t)k * DIM_HID + b]);
        return;
    }
    if (b < WT_BLOCKS) {
        int n = b - DIM_HID;
        for (int k = threadIdx.x; k < DIM_HID; k += blockDim.x)
            W2t[(size_t)n * DIM_HID + k] = __float2half_rn(W2[(size_t)k * DIM_OUT + n]);
        return;
    }
    int i = (b - WT_BLOCKS) * blockDim.x + threadIdx.x;
    if (i >= X_GROUPS) return;
    const float4* src = (const float4*)x;
    float4 v0 = src[2 * i], v1 = src[2 * i + 1];
    uint4 o; __half2 h;
    h = __floats2half2_rn(v0.x, v0.y); o.x = *(unsigned*)&h;
    h = __floats2half2_rn(v0.z, v0.w); o.y = *(unsigned*)&h;
    h = __floats2half2_rn(v1.x, v1.y); o.z = *(unsigned*)&h;
    h = __floats2half2_rn(v1.z, v1.w); o.w = *(unsigned*)&h;
    ((uint4*)xh)[i] = o;
}

// ---------------- convert edges + count degree; block 0 zeroes scan state ----------------
__global__ void convert_edges_kernel(const void* edge, int* cnt,
                                     unsigned long long* __restrict__ state) {
    __shared__ int s_is64;
    if (blockIdx.x == 0 && threadIdx.x < SCAN_BLOCKS)
        state[threadIdx.x] = 0ULL;
    if (threadIdx.x == 0) {
        const long long* e64 = (const long long*)edge;
        int ok = 1;
        #pragma unroll
        for (int i = 0; i < 16; i++) {
            long long v = e64[i];
            if (v < 0 || v >= (long long)N_NODES) { ok = 0; break; }
        }
        s_is64 = ok;
    }
    __syncthreads();
    int i = blockIdx.x * blockDim.x + threadIdx.x;
    if (i >= 2 * N_EDGES) return;
    int v;
    if (s_is64) v = (int)((const long long*)edge)[i];
    else        v = ((const int*)edge)[i];
    if (i < N_EDGES) g_src[i] = v;
    else {
        g_dst[i - N_EDGES] = v;
        atomicAdd(&cnt[v], 1);
    }
}

// ---------------- decoupled-lookback scan; self-cleans cnt ----------------
__global__ __launch_bounds__(1024)
void scan_lookback_kernel(int* __restrict__ cnt,
                          int* __restrict__ row_ptr,
                          float* __restrict__ dinv,
                          int* __restrict__ fill,
                          unsigned long long* __restrict__ state) {
    __shared__ int ws[32];
    __shared__ int s_prefix;
    const int t = threadIdx.x;
    const int lane = t & 31, w = t >> 5;
    const int b = blockIdx.x;
    const int i = b * 1024 + t;

    int val = 0;
    if (i < N_NODES) {
        val = cnt[i];
        cnt[i] = 0;
    }

    int v = val;
    #pragma unroll
    for (int off = 1; off < 32; off <<= 1) {
        int u = __shfl_up_sync(0xffffffffu, v, off);
        if (lane >= off) v += u;
    }
    if (lane == 31) ws[w] = v;
    __syncthreads();
    if (w == 0) {
        int x = ws[lane];
        #pragma unroll
        for (int off = 1; off < 32; off <<= 1) {
            int u = __shfl_up_sync(0xffffffffu, x, off);
            if (lane >= off) x += u;
        }
        ws[lane] = x;
    }
    __syncthreads();
    int incl  = v + (w > 0 ? ws[w - 1] : 0);
    int total = ws[31];

    if (t == 0)
        atomicExch(&state[b], (1ULL << 32) | (unsigned long long)(unsigned)total);

    int partial = 0;
    if (t < b) {
        unsigned long long s;
        do {
            s = *(volatile unsigned long long*)&state[t];
        } while ((s >> 32) == 0ULL);
        partial = (int)(unsigned)s;
    }
    __syncthreads();
    #pragma unroll
    for (int off = 16; off > 0; off >>= 1)
        partial += __shfl_xor_sync(0xffffffffu, partial, off);
    if (lane == 0) ws[w] = partial;
    __syncthreads();
    if (w == 0) {
        int x = ws[lane];
        #pragma unroll
        for (int off = 16; off > 0; off >>= 1)
            x += __shfl_xor_sync(0xffffffffu, x, off);
        if (lane == 0) s_prefix = x;
    }
    __syncthreads();
    int prefix = s_prefix;

    if (i < N_NODES) {
        int excl = prefix + incl - val;
        row_ptr[i] = excl;
        fill[i]    = excl;
        dinv[i]    = rsqrtf((float)val + 1.0f);
    }
    if (b == SCAN_BLOCKS - 1 && t == 0)
        row_ptr[N_NODES] = prefix + total;
}

__global__ void fill_csr_kernel(int* __restrict__ fill,
                                int2* __restrict__ col,
                                const float* __restrict__ dinv) {
    int e = blockIdx.x * blockDim.x + threadIdx.x;
    if (e >= N_EDGES) return;
    int d = g_dst[e];
    int s = g_src[e];
    int pos = atomicAdd(&fill[d], 1);
    col[pos] = make_int2(s, __float_as_int(dinv[s]));
}

// ---------------- fp16 pipelined GEMM (unchanged from R15) ----------------
#define BKH 64

__device__ __forceinline__ uint32_t swz(uint32_t row, uint32_t halfcol) {
    return row * 128u + ((((halfcol >> 3) ^ (row & 7)) << 4) | ((halfcol & 7) << 1));
}

template<int AIT, int BIT>
__device__ __forceinline__ void gemm_issue(
    uint32_t abase, uint32_t bbase,
    const __half* __restrict__ A, const __half* __restrict__ Bt,
    int block_row, int block_col, int M, int K, int k0,
    int ld_row, int ld_chunk)
{
    #pragma unroll
    for (int l = 0; l < AIT; l++) {
        int r  = ld_row + l * 32;
        int gr = block_row + r;
        int sz = (gr < M) ? 16 : 0;
        int grc = (gr < M) ? gr : (M - 1);
        const __half* srcp = A + (size_t)grc * K + k0 + ld_chunk * 8;
        uint32_t dsta = abase + swz((uint32_t)r, (uint32_t)(ld_chunk * 8));
        asm volatile("cp.async.cg.shared.global [%0], [%1], 16, %2;"
                     :: "r"(dsta), "l"(srcp), "r"(sz));
    }
    #pragma unroll
    for (int l = 0; l < BIT; l++) {
        int n = ld_row + l * 32;
        const __half* srcp = Bt + (size_t)(block_col + n) * K + k0 + ld_chunk * 8;
        uint32_t dstb = bbase + swz((uint32_t)n, (uint32_t)(ld_chunk * 8));
        asm volatile("cp.async.cg.shared.global [%0], [%1], 16, 16;"
                     :: "r"(dstb), "l"(srcp));
    }
}

__device__ __forceinline__ void gemm_compute(
    uint32_t abase, uint32_t bbase,
    int wr, int wc, int lane,
    float (&acc)[2][4][4])
{
    #pragma unroll
    for (int kk = 0; kk < BKH; kk += 16) {
        uint32_t fa[2][4];
        uint32_t fb[2][4];
        #pragma unroll
        for (int mt = 0; mt < 2; mt++) {
            uint32_t arow = (uint32_t)(wr + mt * 16 + (lane & 15));
            uint32_t acol = (uint32_t)(kk + ((lane >> 4) << 3));
            uint32_t aaddr = abase + swz(arow, acol);
            asm volatile("ldmatrix.sync.aligned.m8n8.x4.shared.b16 {%0,%1,%2,%3}, [%4];"
                : "=r"(fa[mt][0]), "=r"(fa[mt][1]), "=r"(fa[mt][2]), "=r"(fa[mt][3])
                : "r"(aaddr));
        }
        #pragma unroll
        for (int np = 0; np < 2; np++) {
            uint32_t grp  = (uint32_t)(lane >> 3);
            uint32_t brow = (uint32_t)(wc + np * 16 + (lane & 7)) + ((grp >> 1) << 3);
            uint32_t bcol = (uint32_t)kk + ((grp & 1) << 3);
            uint32_t baddr = bbase + swz(brow, bcol);
            asm volatile("ldmatrix.sync.aligned.m8n8.x4.shared.b16 {%0,%1,%2,%3}, [%4];"
                : "=r"(fb[np][0]), "=r"(fb[np][1]), "=r"(fb[np][2]), "=r"(fb[np][3])
                : "r"(baddr));
        }
        #pragma unroll
        for (int mt = 0; mt < 2; mt++) {
            #pragma unroll
            for (int nt = 0; nt < 4; nt++) {
                uint32_t bb0 = fb[nt >> 1][(nt & 1) * 2];
                uint32_t bb1 = fb[nt >> 1][(nt & 1) * 2 + 1];
                asm volatile(
                    "mma.sync.aligned.m16n8k16.row.col.f32.f16.f16.f32 "
                    "{%0,%1,%2,%3}, {%4,%5,%6,%7}, {%8,%9}, {%0,%1,%2,%3};"
                    : "+f"(acc[mt][nt][0]), "+f"(acc[mt][nt][1]),
                      "+f"(acc[mt][nt][2]), "+f"(acc[mt][nt][3])
                    : "r"(fa[mt][0]), "r"(fa[mt][1]), "r"(fa[mt][2]), "r"(fa[mt][3]),
                      "r"(bb0), "r"(bb1));
            }
        }
    }
}

template<bool WIDE>
__global__ __launch_bounds__(256)
void gemm_fp16_pipe(const __half* __restrict__ A,
                    const __half* __restrict__ Bt,
                    __half* __restrict__ H,
                    int M, int K, int N) {
    constexpr int BM = WIDE ? 64 : 128;
    constexpr int BN = WIDE ? 128 : 64;
    constexpr int A_TILE = BM * BKH * 2;
    constexpr int B_TILE = BN * BKH * 2;
    constexpr int STAGE  = A_TILE + B_TILE;

    __shared__ char smem[2 * STAGE];
    uint32_t sbase = (uint32_t)__cvta_generic_to_shared(smem);

    const int tid  = threadIdx.x;
    const int warp = tid >> 5;
    const int lane = tid & 31;
    const int wr = WIDE ? (warp & 1) * 32 : (warp & 3) * 32;
    const int wc = WIDE ? (warp >> 1) * 32 : (warp >> 2) * 32;
    const int block_row = blockIdx.y * BM;
    const int block_col = blockIdx.x * BN;
    const int lq = lane >> 2;
    const int lr = lane & 3;

    float acc[2][4][4];
    #pragma unroll
    for (int mt = 0; mt < 2; mt++)
        #pragma unroll
        for (int nt = 0; nt < 4; nt++)
            #pragma unroll
            for (int i = 0; i < 4; i++) acc[mt][nt][i] = 0.0f;

    const int ld_row   = tid >> 3;
    const int ld_chunk = tid & 7;

    constexpr int AIT = BM / 32;
    constexpr int BIT = BN / 32;

    const int NIT = K / BKH;
    gemm_issue<AIT, BIT>(sbase, sbase + A_TILE, A, Bt, block_row, block_col, M, K, 0,
                         ld_row, ld_chunk);
    asm volatile("cp.async.commit_group;");

    for (int it = 0; it < NIT; it++) {
        if (it + 1 < NIT) {
            uint32_t nb = sbase + ((it + 1) & 1) * STAGE;
            gemm_issue<AIT, BIT>(nb, nb + A_TILE, A, Bt, block_row, block_col, M, K,
                                 (it + 1) * BKH, ld_row, ld_chunk);
            asm volatile("cp.async.commit_group;");
            asm volatile("cp.async.wait_group 1;");
        } else {
            asm volatile("cp.async.wait_group 0;");
        }
        __syncthreads();
        uint32_t cb = sbase + (it & 1) * STAGE;
        gemm_compute(cb, cb + A_TILE, wr, wc, lane, acc);
        __syncthreads();
    }

    #pragma unroll
    for (int mt = 0; mt < 2; mt++) {
        int r0 = block_row + wr + mt * 16 + lq;
        int r1 = r0 + 8;
        #pragma unroll
        for (int nt = 0; nt < 4; nt++) {
            int c = block_col + wc + nt * 8 + lr * 2;
            if (r0 < M)
                *(__half2*)&H[(size_t)r0 * N + c] = __floats2half2_rn(acc[mt][nt][0], acc[mt][nt][1]);
            if (r1 < M)
                *(__half2*)&H[(size_t)r1 * N + c] = __floats2half2_rn(acc[mt][nt][2], acc[mt][nt][3]);
        }
    }
}

// ---------------- sub-warp gather + bias + (relu) + gate ----------------
// LPE lanes per edge (uint4 = 8 channels per lane); SUBS edges in flight.
// acc double-counts across subs; final shfl-reduce combines; dot scaled 1/SUBS.
__device__ __forceinline__ void add8(float (&acc)[8], uint4 u, float w) {
    float2 f0 = __half22float2(*(__half2*)&u.x);
    float2 f1 = __half22float2(*(__half2*)&u.y);
    float2 f2 = __half22float2(*(__half2*)&u.z);
    float2 f3 = __half22float2(*(__half2*)&u.w);
    acc[0] += f0.x * w; acc[1] += f0.y * w;
    acc[2] += f1.x * w; acc[3] += f1.y * w;
    acc[4] += f2.x * w; acc[5] += f2.y * w;
    acc[6] += f3.x * w; acc[7] += f3.y * w;
}

template<int C, bool RELU, bool OUT_HALF>
__global__ void gather_gate_kernel(const __half* __restrict__ h,
                                   const int* __restrict__ row_ptr,
                                   const int2* __restrict__ col,
                                   const float* __restrict__ dinv,
                                   const float* __restrict__ bias,
                                   const float* __restrict__ aw,
                                   const float* __restrict__ ab,
                                   void* __restrict__ out) {
    constexpr int LPE  = C / 8;          // 16 (C=128) or 8 (C=64)
    constexpr int SUBS = 32 / LPE;       // 2 or 4
    constexpr int Q    = 16 / SUBS;      // loads per lane per 16-edge batch
    constexpr int RST  = C / 8;          // uint4 per row

    int gw   = (blockIdx.x * blockDim.x + threadIdx.x) >> 5;
    int lane = threadIdx.x & 31;
    if (gw >= N_NODES) return;
    int sub = lane / LPE;
    int li  = lane % LPE;

    const uint4* base = (const uint4*)h;
    float di = dinv[gw];

    float acc[8];
    #pragma unroll
    for (int i = 0; i < 8; i++) acc[i] = 0.0f;

    if (sub == 0) {
        uint4 u = base[(size_t)gw * RST + li];
        add8(acc, u, di);                  // self loop (scaled again by di below)
    }

    int p = row_ptr[gw], pe = row_ptr[gw + 1];
    for (; p + 16 <= pe; p += 16) {
        int2 e[Q]; uint4 ui[Q];
        #pragma unroll
        for (int q = 0; q < Q; q++) e[q] = col[p + SUBS * q + sub];
        #pragma unroll
        for (int q = 0; q < Q; q++) ui[q] = base[(size_t)e[q].x * RST + li];
        #pragma unroll
        for (int q = 0; q < Q; q++) add8(acc, ui[q], __int_as_float(e[q].y));
    }
    for (; p + SUBS <= pe; p += SUBS) {
        int2 ec = col[p + sub];
        uint4 u = base[(size_t)ec.x * RST + li];
        add8(acc, u, __int_as_float(ec.y));
    }
    int rem = pe - p;
    if (sub < rem) {
        int2 ec = col[p + sub];
        uint4 u = base[(size_t)ec.x * RST + li];
        add8(acc, u, __int_as_float(ec.y));
    }

    // combine sub-warp partials
    #pragma unroll
    for (int off = LPE; off < 32; off <<= 1) {
        #pragma unroll
        for (int i = 0; i < 8; i++)
            acc[i] += __shfl_xor_sync(0xffffffffu, acc[i], off);
    }

    // epilogue: z = [relu](acc*di + b); gate
    float4 b0 = ((const float4*)bias)[li * 2];
    float4 b1 = ((const float4*)bias)[li * 2 + 1];
    float z[8];
    z[0] = acc[0] * di + b0.x; z[1] = acc[1] * di + b0.y;
    z[2] = acc[2] * di + b0.z; z[3] = acc[3] * di + b0.w;
    z[4] = acc[4] * di + b1.x; z[5] = acc[5] * di + b1.y;
    z[6] = acc[6] * di + b1.z; z[7] = acc[7] * di + b1.w;
    if (RELU) {
        #pragma unroll
        for (int i = 0; i < 8; i++) z[i] = fmaxf(z[i], 0.0f);
    }
    float4 a0 = ((const float4*)aw)[li * 2];
    float4 a1 = ((const float4*)aw)[li * 2 + 1];
    float dot = z[0]*a0.x + z[1]*a0.y + z[2]*a0.z + z[3]*a0.w
              + z[4]*a1.x + z[5]*a1.y + z[6]*a1.z + z[7]*a1.w;
    #pragma unroll
    for (int off = 16; off > 0; off >>= 1)
        dot += __shfl_xor_sync(0xffffffffu, dot, off);
    dot *= (1.0f / SUBS);
    float g = 1.0f / (1.0f + expf(-(dot + ab[0])));
    #pragma unroll
    for (int i = 0; i < 8; i++) z[i] *= g;

    if (sub == 0) {
        if constexpr (OUT_HALF) {
            __half2 h0 = __floats2half2_rn(z[0], z[1]);
            __half2 h1 = __floats2half2_rn(z[2], z[3]);
            __half2 h2 = __floats2half2_rn(z[4], z[5]);
            __half2 h3 = __floats2half2_rn(z[6], z[7]);
            uint4 uo;
            uo.x = *(unsigned*)&h0; uo.y = *(unsigned*)&h1;
            uo.z = *(unsigned*)&h2; uo.w = *(unsigned*)&h3;
            ((uint4*)out)[(size_t)gw * RST + li] = uo;
        } else {
            // fp32 out: row = C floats = C/4 float4; lane li stores 2 float4
            float4 o0 = make_float4(z[0], z[1], z[2], z[3]);
            float4 o1 = make_float4(z[4], z[5], z[6], z[7]);
            ((float4*)out)[(size_t)gw * (C / 4) + li * 2]     = o0;
            ((float4*)out)[(size_t)gw * (C / 4) + li * 2 + 1] = o1;
        }
    }
}

// ---------------- launch ----------------
extern "C" void kernel_launch(void* const* d_in, const int* in_sizes, int n_in,
                              void* d_out, int out_size) {
    const float* x    = (const float*)d_in[0];
    const void*  edge = d_in[1];
    const float* W1  = (const float*)d_in[2];
    const float* b1  = (const float*)d_in[3];
    const float* W2  = (const float*)d_in[4];
    const float* b2  = (const float*)d_in[5];
    const float* aw1 = (const float*)d_in[6];
    const float* ab1 = (const float*)d_in[7];
    const float* aw2 = (const float*)d_in[8];
    const float* ab2 = (const float*)d_in[9];
    float* out = (float*)d_out;

    float *dinv;
    __half *xh, *w1t, *w2t, *h1, *y1, *h2;
    int *cnt, *row_ptr, *fill;
    int2 *col;
    unsigned long long *state;
    cudaGetSymbolAddress((void**)&dinv,    g_dinv);
    cudaGetSymbolAddress((void**)&xh,      g_xh);
    cudaGetSymbolAddress((void**)&w1t,     g_w1t);
    cudaGetSymbolAddress((void**)&w2t,     g_w2t);
    cudaGetSymbolAddress((void**)&h1,      g_h1);
    cudaGetSymbolAddress((void**)&y1,      g_y1);
    cudaGetSymbolAddress((void**)&h2,      g_h2);
    cudaGetSymbolAddress((void**)&cnt,     g_cnt);
    cudaGetSymbolAddress((void**)&row_ptr, g_row_ptr);
    cudaGetSymbolAddress((void**)&fill,    g_fill);
    cudaGetSymbolAddress((void**)&col,     g_col);
    cudaGetSymbolAddress((void**)&state,   g_scanstate);

    static cudaStream_t s1 = nullptr;
    static cudaEvent_t evA = nullptr, evB = nullptr;
    if (s1 == nullptr) {
        cudaStreamCreateWithFlags(&s1, cudaStreamNonBlocking);
        cudaEventCreateWithFlags(&evA, cudaEventDisableTiming);
        cudaEventCreateWithFlags(&evB, cudaEventDisableTiming);
    }

    const int T = 256;

    // fork
    cudaEventRecord(evA, 0);
    cudaStreamWaitEvent(s1, evA, 0);

    // s1: CSR chain
    convert_edges_kernel<<<(2 * N_EDGES + T - 1) / T, T, 0, s1>>>(edge, cnt, state);
    scan_lookback_kernel<<<SCAN_BLOCKS, 1024, 0, s1>>>(cnt, row_ptr, dinv, fill, state);
    fill_csr_kernel<<<(N_EDGES + T - 1) / T, T, 0, s1>>>(fill, col, dinv);
    cudaEventRecord(evB, s1);

    // main: fused conversion, then GEMM1 (BN=128, A read once)
    convert_all_kernel<<<WT_BLOCKS + (X_GROUPS + T - 1) / T, T>>>(x, xh, W1, w1t, W2, w2t);
    {
        dim3 grid(1, (N_NODES + 63) / 64);
        gemm_fp16_pipe<true><<<grid, 256>>>(xh, w1t, h1, N_NODES, DIM_IN, DIM_HID);
    }

    // join with CSR
    cudaStreamWaitEvent(0, evB, 0);

    gather_gate_kernel<DIM_HID, true, true><<<(N_NODES * 32 + T - 1) / T, T>>>(
        h1, row_ptr, col, dinv, b1, aw1, ab1, y1);

    {
        dim3 grid(1, (N_NODES + 127) / 128);
        gemm_fp16_pipe<false><<<grid, 256>>>(y1, w2t, h2, N_NODES, DIM_HID, DIM_OUT);
    }

    gather_gate_kernel<DIM_OUT, false, false><<<(N_NODES * 32 + T - 1) / T, T>>>(
        h2, row_ptr, col, dinv, b2, aw2, ab2, out);
}

// round 17
// speedup vs baseline: 1.0664x; 1.0664x over previous
#include <cuda_runtime.h>
#include <cuda_fp16.h>
#include <stdint.h>
#include <math.h>

#define N_NODES 50000
#define N_EDGES 800000
#define DIM_IN  256
#define DIM_HID 128
#define DIM_OUT 64
#define SCAN_BLOCKS ((N_NODES + 1023) / 1024)   // 49

// ---------------- device scratch (no allocation allowed) ----------------
// g_cnt / g_scanstate: zero at load; self-cleaned every call (deterministic).
__device__ float  g_dinv[N_NODES];
__device__ __half g_xh[N_NODES * DIM_IN];
__device__ __half g_w1t[DIM_HID * DIM_IN];   // W1^T fp16 [N][K]
__device__ __half g_w2t[DIM_OUT * DIM_HID];  // W2^T fp16 [N][K]
__device__ __half g_h1[N_NODES * DIM_HID];
__device__ __half g_y1[N_NODES * DIM_HID];
__device__ __half g_h2[N_NODES * DIM_OUT];
__device__ int   g_dst[N_EDGES];
__device__ int   g_cnt[N_NODES];
__device__ int   g_row_ptr[N_NODES + 1];
__device__ int   g_fill[N_NODES];
__device__ int2  g_col[N_EDGES];             // packed {src, dinv[src] bits}
__device__ unsigned long long g_scanstate[SCAN_BLOCKS];

__device__ __forceinline__ int edge_is64(const void* edge) {
    const long long* e64 = (const long long*)edge;
    int ok = 1;
    #pragma unroll
    for (int i = 0; i < 16; i++) {
        long long v = e64[i];
        if (v < 0 || v >= (long long)N_NODES) { ok = 0; break; }
    }
    return ok;
}

// ---------------- fused converter: blocks [0,192) weights, rest x ----------------
#define WT_BLOCKS (DIM_HID + DIM_OUT)        // 192
#define X_GROUPS  (N_NODES * DIM_IN / 8)
__global__ void convert_all_kernel(const float* __restrict__ x,
                                   __half* __restrict__ xh,
                                   const float* __restrict__ W1,
                                   __half* __restrict__ W1t,
                                   const float* __restrict__ W2,
                                   __half* __restrict__ W2t) {
    int b = blockIdx.x;
    if (b < DIM_HID) {
        for (int k = threadIdx.x; k < DIM_IN; k += blockDim.x)
            W1t[(size_t)b * DIM_IN + k] = __float2half_rn(W1[(size_t)k * DIM_HID + b]);
        return;
    }
    if (b < WT_BLOCKS) {
        int n = b - DIM_HID;
        for (int k = threadIdx.x; k < DIM_HID; k += blockDim.x)
            W2t[(size_t)n * DIM_HID + k] = __float2half_rn(W2[(size_t)k * DIM_OUT + n]);
        return;
    }
    int i = (b - WT_BLOCKS) * blockDim.x + threadIdx.x;
    if (i >= X_GROUPS) return;
    const float4* src = (const float4*)x;
    float4 v0 = src[2 * i], v1 = src[2 * i + 1];
    uint4 o; __half2 h;
    h = __floats2half2_rn(v0.x, v0.y); o.x = *(unsigned*)&h;
    h = __floats2half2_rn(v0.z, v0.w); o.y = *(unsigned*)&h;
    h = __floats2half2_rn(v1.x, v1.y); o.z = *(unsigned*)&h;
    h = __floats2half2_rn(v1.z, v1.w); o.w = *(unsigned*)&h;
    ((uint4*)xh)[i] = o;
}

// ---------------- dst conversion + degree count; block 0 zeroes scan state ----------------
__global__ void convert_dst_kernel(const void* edge, int* cnt,
                                   unsigned long long* __restrict__ state) {
    __shared__ int s_is64;
    if (blockIdx.x == 0 && threadIdx.x < SCAN_BLOCKS)
        state[threadIdx.x] = 0ULL;
    if (threadIdx.x == 0) s_is64 = edge_is64(edge);
    __syncthreads();
    int i = blockIdx.x * blockDim.x + threadIdx.x;
    if (i >= N_EDGES) return;
    int v;
    if (s_is64) v = (int)((const long long*)edge)[N_EDGES + i];
    else        v = ((const int*)edge)[N_EDGES + i];
    g_dst[i] = v;
    atomicAdd(&cnt[v], 1);
}

// ---------------- decoupled-lookback scan; self-cleans cnt ----------------
__global__ __launch_bounds__(1024)
void scan_lookback_kernel(int* __restrict__ cnt,
                          int* __restrict__ row_ptr,
                          float* __restrict__ dinv,
                          int* __restrict__ fill,
                          unsigned long long* __restrict__ state) {
    __shared__ int ws[32];
    __shared__ int s_prefix;
    const int t = threadIdx.x;
    const int lane = t & 31, w = t >> 5;
    const int b = blockIdx.x;
    const int i = b * 1024 + t;

    int val = 0;
    if (i < N_NODES) {
        val = cnt[i];
        cnt[i] = 0;
    }

    int v = val;
    #pragma unroll
    for (int off = 1; off < 32; off <<= 1) {
        int u = __shfl_up_sync(0xffffffffu, v, off);
        if (lane >= off) v += u;
    }
    if (lane == 31) ws[w] = v;
    __syncthreads();
    if (w == 0) {
        int x = ws[lane];
        #pragma unroll
        for (int off = 1; off < 32; off <<= 1) {
            int u = __shfl_up_sync(0xffffffffu, x, off);
            if (lane >= off) x += u;
        }
        ws[lane] = x;
    }
    __syncthreads();
    int incl  = v + (w > 0 ? ws[w - 1] : 0);
    int total = ws[31];

    if (t == 0)
        atomicExch(&state[b], (1ULL << 32) | (unsigned long long)(unsigned)total);

    int partial = 0;
    if (t < b) {
        unsigned long long s;
        do {
            s = *(volatile unsigned long long*)&state[t];
        } while ((s >> 32) == 0ULL);
        partial = (int)(unsigned)s;
    }
    __syncthreads();
    #pragma unroll
    for (int off = 16; off > 0; off >>= 1)
        partial += __shfl_xor_sync(0xffffffffu, partial, off);
    if (lane == 0) ws[w] = partial;
    __syncthreads();
    if (w == 0) {
        int x = ws[lane];
        #pragma unroll
        for (int off = 16; off > 0; off >>= 1)
            x += __shfl_xor_sync(0xffffffffu, x, off);
        if (lane == 0) s_prefix = x;
    }
    __syncthreads();
    int prefix = s_prefix;

    if (i < N_NODES) {
        int excl = prefix + incl - val;
        row_ptr[i] = excl;
        fill[i]    = excl;
        dinv[i]    = rsqrtf((float)val + 1.0f);
    }
    if (b == SCAN_BLOCKS - 1 && t == 0)
        row_ptr[N_NODES] = prefix + total;
}

// fill CSR: src read directly from edge buffer (L2-hot second pass)
__global__ void fill_csr_kernel(const void* edge,
                                int* __restrict__ fill,
                                int2* __restrict__ col,
                                const float* __restrict__ dinv) {
    __shared__ int s_is64;
    if (threadIdx.x == 0) s_is64 = edge_is64(edge);
    __syncthreads();
    int e = blockIdx.x * blockDim.x + threadIdx.x;
    if (e >= N_EDGES) return;
    int s;
    if (s_is64) s = (int)((const long long*)edge)[e];
    else        s = ((const int*)edge)[e];
    int d = g_dst[e];
    int pos = atomicAdd(&fill[d], 1);
    col[pos] = make_int2(s, __float_as_int(dinv[s]));
}

// ---------------- fp16 pipelined GEMM (unchanged) ----------------
#define BKH 64

__device__ __forceinline__ uint32_t swz(uint32_t row, uint32_t halfcol) {
    return row * 128u + ((((halfcol >> 3) ^ (row & 7)) << 4) | ((halfcol & 7) << 1));
}

template<int AIT, int BIT>
__device__ __forceinline__ void gemm_issue(
    uint32_t abase, uint32_t bbase,
    const __half* __restrict__ A, const __half* __restrict__ Bt,
    int block_row, int block_col, int M, int K, int k0,
    int ld_row, int ld_chunk)
{
    #pragma unroll
    for (int l = 0; l < AIT; l++) {
        int r  = ld_row + l * 32;
        int gr = block_row + r;
        int sz = (gr < M) ? 16 : 0;
        int grc = (gr < M) ? gr : (M - 1);
        const __half* srcp = A + (size_t)grc * K + k0 + ld_chunk * 8;
        uint32_t dsta = abase + swz((uint32_t)r, (uint32_t)(ld_chunk * 8));
        asm volatile("cp.async.cg.shared.global [%0], [%1], 16, %2;"
                     :: "r"(dsta), "l"(srcp), "r"(sz));
    }
    #pragma unroll
    for (int l = 0; l < BIT; l++) {
        int n = ld_row + l * 32;
        const __half* srcp = Bt + (size_t)(block_col + n) * K + k0 + ld_chunk * 8;
        uint32_t dstb = bbase + swz((uint32_t)n, (uint32_t)(ld_chunk * 8));
        asm volatile("cp.async.cg.shared.global [%0], [%1], 16, 16;"
                     :: "r"(dstb), "l"(srcp));
    }
}

__device__ __forceinline__ void gemm_compute(
    uint32_t abase, uint32_t bbase,
    int wr, int wc, int lane,
    float (&acc)[2][4][4])
{
    #pragma unroll
    for (int kk = 0; kk < BKH; kk += 16) {
        uint32_t fa[2][4];
        uint32_t fb[2][4];
        #pragma unroll
        for (int mt = 0; mt < 2; mt++) {
            uint32_t arow = (uint32_t)(wr + mt * 16 + (lane & 15));
            uint32_t acol = (uint32_t)(kk + ((lane >> 4) << 3));
            uint32_t aaddr = abase + swz(arow, acol);
            asm volatile("ldmatrix.sync.aligned.m8n8.x4.shared.b16 {%0,%1,%2,%3}, [%4];"
                : "=r"(fa[mt][0]), "=r"(fa[mt][1]), "=r"(fa[mt][2]), "=r"(fa[mt][3])
                : "r"(aaddr));
        }
        #pragma unroll
        for (int np = 0; np < 2; np++) {
            uint32_t grp  = (uint32_t)(lane >> 3);
            uint32_t brow = (uint32_t)(wc + np * 16 + (lane & 7)) + ((grp >> 1) << 3);
            uint32_t bcol = (uint32_t)kk + ((grp & 1) << 3);
            uint32_t baddr = bbase + swz(brow, bcol);
            asm volatile("ldmatrix.sync.aligned.m8n8.x4.shared.b16 {%0,%1,%2,%3}, [%4];"
                : "=r"(fb[np][0]), "=r"(fb[np][1]), "=r"(fb[np][2]), "=r"(fb[np][3])
                : "r"(baddr));
        }
        #pragma unroll
        for (int mt = 0; mt < 2; mt++) {
            #pragma unroll
            for (int nt = 0; nt < 4; nt++) {
                uint32_t bb0 = fb[nt >> 1][(nt & 1) * 2];
                uint32_t bb1 = fb[nt >> 1][(nt & 1) * 2 + 1];
                asm volatile(
                    "mma.sync.aligned.m16n8k16.row.col.f32.f16.f16.f32 "
                    "{%0,%1,%2,%3}, {%4,%5,%6,%7}, {%8,%9}, {%0,%1,%2,%3};"
                    : "+f"(acc[mt][nt][0]), "+f"(acc[mt][nt][1]),
                      "+f"(acc[mt][nt][2]), "+f"(acc[mt][nt][3])
                    : "r"(fa[mt][0]), "r"(fa[mt][1]), "r"(fa[mt][2]), "r"(fa[mt][3]),
                      "r"(bb0), "r"(bb1));
            }
        }
    }
}

template<bool WIDE>
__global__ __launch_bounds__(256)
void gemm_fp16_pipe(const __half* __restrict__ A,
                    const __half* __restrict__ Bt,
                    __half* __restrict__ H,
                    int M, int K, int N) {
    constexpr int BM = WIDE ? 64 : 128;
    constexpr int BN = WIDE ? 128 : 64;
    constexpr int A_TILE = BM * BKH * 2;
    constexpr int B_TILE = BN * BKH * 2;
    constexpr int STAGE  = A_TILE + B_TILE;

    __shared__ char smem[2 * STAGE];
    uint32_t sbase = (uint32_t)__cvta_generic_to_shared(smem);

    const int tid  = threadIdx.x;
    const int warp = tid >> 5;
    const int lane = tid & 31;
    const int wr = WIDE ? (warp & 1) * 32 : (warp & 3) * 32;
    const int wc = WIDE ? (warp >> 1) * 32 : (warp >> 2) * 32;
    const int block_row = blockIdx.y * BM;
    const int block_col = blockIdx.x * BN;
    const int lq = lane >> 2;
    const int lr = lane & 3;

    float acc[2][4][4];
    #pragma unroll
    for (int mt = 0; mt < 2; mt++)
        #pragma unroll
        for (int nt = 0; nt < 4; nt++)
            #pragma unroll
            for (int i = 0; i < 4; i++) acc[mt][nt][i] = 0.0f;

    const int ld_row   = tid >> 3;
    const int ld_chunk = tid & 7;

    constexpr int AIT = BM / 32;
    constexpr int BIT = BN / 32;

    const int NIT = K / BKH;
    gemm_issue<AIT, BIT>(sbase, sbase + A_TILE, A, Bt, block_row, block_col, M, K, 0,
                         ld_row, ld_chunk);
    asm volatile("cp.async.commit_group;");

    for (int it = 0; it < NIT; it++) {
        if (it + 1 < NIT) {
            uint32_t nb = sbase + ((it + 1) & 1) * STAGE;
            gemm_issue<AIT, BIT>(nb, nb + A_TILE, A, Bt, block_row, block_col, M, K,
                                 (it + 1) * BKH, ld_row, ld_chunk);
            asm volatile("cp.async.commit_group;");
            asm volatile("cp.async.wait_group 1;");
        } else {
            asm volatile("cp.async.wait_group 0;");
        }
        __syncthreads();
        uint32_t cb = sbase + (it & 1) * STAGE;
        gemm_compute(cb, cb + A_TILE, wr, wc, lane, acc);
        __syncthreads();
    }

    #pragma unroll
    for (int mt = 0; mt < 2; mt++) {
        int r0 = block_row + wr + mt * 16 + lq;
        int r1 = r0 + 8;
        #pragma unroll
        for (int nt = 0; nt < 4; nt++) {
            int c = block_col + wc + nt * 8 + lr * 2;
            if (r0 < M)
                *(__half2*)&H[(size_t)r0 * N + c] = __floats2half2_rn(acc[mt][nt][0], acc[mt][nt][1]);
            if (r1 < M)
                *(__half2*)&H[(size_t)r1 * N + c] = __floats2half2_rn(acc[mt][nt][2], acc[mt][nt][3]);
        }
    }
}

// ---------------- fused CSR gather (R15-proven version) ----------------
template<int C, bool RELU, bool OUT_HALF>
__global__ void gather_gate_kernel(const __half* __restrict__ h,
                                   const int* __restrict__ row_ptr,
                                   const int2* __restrict__ col,
                                   const float* __restrict__ dinv,
                                   const float* __restrict__ bias,
                                   const float* __restrict__ aw,
                                   const float* __restrict__ ab,
                                   void* __restrict__ out) {
    int gw   = (blockIdx.x * blockDim.x + threadIdx.x) >> 5;
    int lane = threadIdx.x & 31;
    if (gw >= N_NODES) return;

    float di = dinv[gw];

    if constexpr (C == 128) {
        const uint2* base = (const uint2*)h;
        uint2 u = base[(size_t)gw * 32 + lane];
        float2 p0 = __half22float2(*(__half2*)&u.x);
        float2 p1 = __half22float2(*(__half2*)&u.y);
        float4 acc = make_float4(p0.x * di, p0.y * di, p1.x * di, p1.y * di);

        int p = row_ptr[gw], pe = row_ptr[gw + 1];
        for (; p + 8 <= pe; p += 8) {
            int2 e[8]; uint2 ui[8];
            #pragma unroll
            for (int q = 0; q < 8; q++) e[q] = col[p + q];
            #pragma unroll
            for (int q = 0; q < 8; q++) ui[q] = base[(size_t)e[q].x * 32 + lane];
            #pragma unroll
            for (int q = 0; q < 8; q++) {
                float w = __int_as_float(e[q].y);
                float2 a = __half22float2(*(__half2*)&ui[q].x);
                float2 b = __half22float2(*(__half2*)&ui[q].y);
                acc.x += a.x * w; acc.y += a.y * w;
                acc.z += b.x * w; acc.w += b.y * w;
            }
        }
        for (; p < pe; p++) {
            int2 ec = col[p];
            float w = __int_as_float(ec.y);
            uint2 us = base[(size_t)ec.x * 32 + lane];
            float2 a = __half22float2(*(__half2*)&us.x);
            float2 b = __half22float2(*(__half2*)&us.y);
            acc.x += a.x*w; acc.y += a.y*w; acc.z += b.x*w; acc.w += b.y*w;
        }
        float4 b = ((const float4*)bias)[lane];
        float4 z;
        z.x = acc.x * di + b.x; z.y = acc.y * di + b.y;
        z.z = acc.z * di + b.z; z.w = acc.w * di + b.w;
        if (RELU) {
            z.x = fmaxf(z.x, 0.f); z.y = fmaxf(z.y, 0.f);
            z.z = fmaxf(z.z, 0.f); z.w = fmaxf(z.w, 0.f);
        }
        float4 a = ((const float4*)aw)[lane];
        float dot = z.x * a.x + z.y * a.y + z.z * a.z + z.w * a.w;
        #pragma unroll
        for (int off = 16; off > 0; off >>= 1)
            dot += __shfl_xor_sync(0xffffffffu, dot, off);
        float g = 1.0f / (1.0f + expf(-(dot + ab[0])));
        z.x *= g; z.y *= g; z.z *= g; z.w *= g;
        if constexpr (OUT_HALF) {
            __half2 z01 = __floats2half2_rn(z.x, z.y);
            __half2 z23 = __floats2half2_rn(z.z, z.w);
            uint2 uo;
            uo.x = *(unsigned*)&z01; uo.y = *(unsigned*)&z23;
            ((uint2*)out)[(size_t)gw * 32 + lane] = uo;
        } else {
            ((float4*)out)[(size_t)gw * 32 + lane] = z;
        }
    } else {
        const unsigned* base = (const unsigned*)h;
        unsigned u = base[(size_t)gw * 32 + lane];
        float2 ps = __half22float2(*(__half2*)&u);
        float2 acc = make_float2(ps.x * di, ps.y * di);

        int p = row_ptr[gw], pe = row_ptr[gw + 1];
        for (; p + 8 <= pe; p += 8) {
            int2 e[8]; unsigned ui[8];
            #pragma unroll
            for (int q = 0; q < 8; q++) e[q] = col[p + q];
            #pragma unroll
            for (int q = 0; q < 8; q++) ui[q] = base[(size_t)e[q].x * 32 + lane];
            #pragma unroll
            for (int q = 0; q < 8; q++) {
                float w = __int_as_float(e[q].y);
                float2 v = __half22float2(*(__half2*)&ui[q]);
                acc.x += v.x * w; acc.y += v.y * w;
            }
        }
        for (; p < pe; p++) {
            int2 ec = col[p];
            float w = __int_as_float(ec.y);
            unsigned us = base[(size_t)ec.x * 32 + lane];
            float2 v = __half22float2(*(__half2*)&us);
            acc.x += v.x*w; acc.y += v.y*w;
        }
        float2 b = ((const float2*)bias)[lane];
        float2 z;
        z.x = acc.x * di + b.x; z.y = acc.y * di + b.y;
        if (RELU) { z.x = fmaxf(z.x, 0.f); z.y = fmaxf(z.y, 0.f); }
        float2 a = ((const float2*)aw)[lane];
        float dot = z.x * a.x + z.y * a.y;
        #pragma unroll
        for (int off = 16; off > 0; off >>= 1)
            dot += __shfl_xor_sync(0xffffffffu, dot, off);
        float g = 1.0f / (1.0f + expf(-(dot + ab[0])));
        z.x *= g; z.y *= g;
        if constexpr (OUT_HALF) {
            __half2 zo = __floats2half2_rn(z.x, z.y);
            ((unsigned*)out)[(size_t)gw * 32 + lane] = *(unsigned*)&zo;
        } else {
            ((float2*)out)[(size_t)gw * 32 + lane] = z;
        }
    }
}

// ---------------- launch ----------------
extern "C" void kernel_launch(void* const* d_in, const int* in_sizes, int n_in,
                              void* d_out, int out_size) {
    const float* x    = (const float*)d_in[0];
    const void*  edge = d_in[1];
    const float* W1  = (const float*)d_in[2];
    const float* b1  = (const float*)d_in[3];
    const float* W2  = (const float*)d_in[4];
    const float* b2  = (const float*)d_in[5];
    const float* aw1 = (const float*)d_in[6];
    const float* ab1 = (const float*)d_in[7];
    const float* aw2 = (const float*)d_in[8];
    const float* ab2 = (const float*)d_in[9];
    float* out = (float*)d_out;

    float *dinv;
    __half *xh, *w1t, *w2t, *h1, *y1, *h2;
    int *cnt, *row_ptr, *fill;
    int2 *col;
    unsigned long long *state;
    cudaGetSymbolAddress((void**)&dinv,    g_dinv);
    cudaGetSymbolAddress((void**)&xh,      g_xh);
    cudaGetSymbolAddress((void**)&w1t,     g_w1t);
    cudaGetSymbolAddress((void**)&w2t,     g_w2t);
    cudaGetSymbolAddress((void**)&h1,      g_h1);
    cudaGetSymbolAddress((void**)&y1,      g_y1);
    cudaGetSymbolAddress((void**)&h2,      g_h2);
    cudaGetSymbolAddress((void**)&cnt,     g_cnt);
    cudaGetSymbolAddress((void**)&row_ptr, g_row_ptr);
    cudaGetSymbolAddress((void**)&fill,    g_fill);
    cudaGetSymbolAddress((void**)&col,     g_col);
    cudaGetSymbolAddress((void**)&state,   g_scanstate);

    static cudaStream_t s1 = nullptr;
    static cudaEvent_t evA = nullptr, evB = nullptr;
    if (s1 == nullptr) {
        cudaStreamCreateWithFlags(&s1, cudaStreamNonBlocking);
        cudaEventCreateWithFlags(&evA, cudaEventDisableTiming);
        cudaEventCreateWithFlags(&evB, cudaEventDisableTiming);
    }

    const int T = 256;

    // fork
    cudaEventRecord(evA, 0);
    cudaStreamWaitEvent(s1, evA, 0);

    // s1: CSR chain (dst-only convert; fill reads src straight from edge buffer)
    convert_dst_kernel<<<(N_EDGES + T - 1) / T, T, 0, s1>>>(edge, cnt, state);
    scan_lookback_kernel<<<SCAN_BLOCKS, 1024, 0, s1>>>(cnt, row_ptr, dinv, fill, state);
    fill_csr_kernel<<<(N_EDGES + T - 1) / T, T, 0, s1>>>(edge, fill, col, dinv);
    cudaEventRecord(evB, s1);

    // main: fused conversion, then GEMM1 (BN=128, A read once)
    convert_all_kernel<<<WT_BLOCKS + (X_GROUPS + T - 1) / T, T>>>(x, xh, W1, w1t, W2, w2t);
    {
        dim3 grid(1, (N_NODES + 63) / 64);
        gemm_fp16_pipe<true><<<grid, 256>>>(xh, w1t, h1, N_NODES, DIM_IN, DIM_HID);
    }

    // join with CSR
    cudaStreamWaitEvent(0, evB, 0);

    gather_gate_kernel<DIM_HID, true, true><<<(N_NODES * 32 + T - 1) / T, T>>>(
        h1, row_ptr, col, dinv, b1, aw1, ab1, y1);

    {
        dim3 grid(1, (N_NODES + 127) / 128);
        gemm_fp16_pipe<false><<<grid, 256>>>(y1, w2t, h2, N_NODES, DIM_HID, DIM_OUT);
    }

    gather_gate_kernel<DIM_OUT, false, false><<<(N_NODES * 32 + T - 1) / T, T>>>(
        h2, row_ptr, col, dinv, b2, aw2, ab2, out);
}